// round 1
// baseline (speedup 1.0000x reference)
#include <cuda_runtime.h>
#include <cuda_bf16.h>

// ---------------------------------------------------------------------------
// GraphSAGE 2-layer (mean aggregation), N=100000 nodes, F: 27 -> 128 -> 64.
//
// Pipeline (all graph-capturable, scratch in __device__ globals):
//   1. detect edge_index dtype (int32 vs int64) on device
//   2. build CSR by dst: count -> 2-level exclusive scan -> bucket scatter
//   3. agg1[n,27]  = mean_{e: dst=n} x[src]              (gather, no fp atomics)
//   4. h[n,128]    = relu(agg1 @ W1_l + x @ W1_r + b1)    (reg-weight GEMM)
//   5. p[n,64]     = h @ W2_l ;  r[n,64] = h @ W2_r       (reg-weight GEMM x2)
//   6. out[n,64]   = mean_{e: dst=n} p[src] + b2 + r[n]   (gather + epilogue)
// Pushing W2_l through the (linear) mean lets layer-2 aggregate 64 floats/edge
// instead of 128.
// ---------------------------------------------------------------------------

#define NN   100000
#define ECAP 1700000

static __device__ int   g_is64;
static __device__ int   g_cnt[NN];
static __device__ int   g_off[NN];
static __device__ int   g_cur[NN];
static __device__ int   g_part[128];
static __device__ int   g_csr[ECAP];
static __device__ float g_agg1[NN * 28];     // padded row: [27]=0
static __device__ float g_h[NN * 128];
static __device__ float g_p[NN * 64];
static __device__ float g_r[NN * 64];

__device__ __forceinline__ int eidx(const int* __restrict__ e, int elem, int is64) {
    // little-endian: low 32 bits of int64 value sit at word 2*elem
    return is64 ? e[2 * elem] : e[elem];
}

// --- dtype detection: int64 values < 2^31 have zero high words --------------
__global__ void k_detect(const int* __restrict__ e) {
    __shared__ int s;
    if (threadIdx.x == 0) s = 0;
    __syncthreads();
    if (e[2 * threadIdx.x + 1] != 0) atomicOr(&s, 1);
    __syncthreads();
    if (threadIdx.x == 0) g_is64 = (s == 0);
}

__global__ void k_zero() {
    int i = blockIdx.x * blockDim.x + threadIdx.x;
    if (i < NN) g_cnt[i] = 0;
}

__global__ void k_count(const int* __restrict__ e, int E) {
    int i = blockIdx.x * blockDim.x + threadIdx.x;
    if (i >= E) return;
    int is64 = g_is64;
    atomicAdd(&g_cnt[eidx(e, E + i, is64)], 1);
}

// --- 2-level exclusive scan of g_cnt -> g_off -------------------------------
__global__ void k_scan_a() {
    __shared__ int s[1024];
    int tid = threadIdx.x;
    int i = blockIdx.x * 1024 + tid;
    int v = (i < NN) ? g_cnt[i] : 0;
    s[tid] = v;
    __syncthreads();
    for (int off = 1; off < 1024; off <<= 1) {
        int t = (tid >= off) ? s[tid - off] : 0;
        __syncthreads();
        s[tid] += t;
        __syncthreads();
    }
    if (i < NN) g_off[i] = s[tid] - v;          // block-local exclusive
    if (tid == 1023) g_part[blockIdx.x] = s[1023];
}

__global__ void k_scan_b(int nb) {
    if (threadIdx.x == 0) {
        int run = 0;
        for (int b = 0; b < nb; b++) { int t = g_part[b]; g_part[b] = run; run += t; }
    }
}

__global__ void k_scan_c() {
    int i = blockIdx.x * blockDim.x + threadIdx.x;
    if (i >= NN) return;
    int o = g_off[i] + g_part[i >> 10];
    g_off[i] = o;
    g_cur[i] = o;
}

__global__ void k_bucket(const int* __restrict__ e, int E) {
    int i = blockIdx.x * blockDim.x + threadIdx.x;
    if (i >= E) return;
    int is64 = g_is64;
    int s = eidx(e, i, is64);
    int d = eidx(e, E + i, is64);
    int pos = atomicAdd(&g_cur[d], 1);
    g_csr[pos] = s;
}

// --- layer-1 aggregation: warp per node, lane = feature ---------------------
__global__ void k_agg1(const float* __restrict__ x) {
    int w    = (blockIdx.x * blockDim.x + threadIdx.x) >> 5;
    int lane = threadIdx.x & 31;
    if (w >= NN) return;
    int start = g_off[w], cnt = g_cnt[w];
    int lf = (lane < 27) ? lane : 0;             // lanes 27..31 load in-bounds junk
    float acc = 0.f;
    int k = 0;
    for (; k + 4 <= cnt; k += 4) {               // 4-deep MLP
        int s0 = g_csr[start + k],     s1 = g_csr[start + k + 1];
        int s2 = g_csr[start + k + 2], s3 = g_csr[start + k + 3];
        float v0 = x[s0 * 27 + lf], v1 = x[s1 * 27 + lf];
        float v2 = x[s2 * 27 + lf], v3 = x[s3 * 27 + lf];
        acc += (v0 + v1) + (v2 + v3);
    }
    for (; k < cnt; k++) acc += x[g_csr[start + k] * 27 + lf];
    float inv = 1.f / (float)(cnt > 0 ? cnt : 1);
    if (lane < 28) g_agg1[w * 28 + lane] = (lane < 27) ? acc * inv : 0.f;
}

// --- GEMM1: h = relu([agg1|x] @ [W1_l;W1_r] + b1) ---------------------------
// thread j holds the full 56-row weight column in registers; inputs staged to
// smem (padded to 56 floats/node) and read back as float4 broadcasts.
__global__ void __launch_bounds__(128) k_gemm1(
    const float* __restrict__ x, const float* __restrict__ W1l,
    const float* __restrict__ b1, const float* __restrict__ W1r) {
    __shared__ float sIn[64][56];                 // [node][agg(28)|x(28)] 14.3KB
    int j  = threadIdx.x;                         // output column 0..127
    int n0 = blockIdx.x * 64;

    float wreg[56];
#pragma unroll
    for (int f = 0; f < 27; f++) {
        wreg[f]      = W1l[f * 128 + j];
        wreg[28 + f] = W1r[f * 128 + j];
    }
    wreg[27] = 0.f; wreg[55] = 0.f;
    float bias = b1[j];

    for (int idx = threadIdx.x; idx < 64 * 28; idx += 128) {
        int r = idx / 28, f = idx % 28;
        int n = n0 + r;
        sIn[r][f]      = (n < NN) ? g_agg1[n * 28 + f] : 0.f;
        sIn[r][28 + f] = (n < NN && f < 27) ? x[n * 27 + f] : 0.f;
    }
    __syncthreads();

    for (int r = 0; r < 64; r += 2) {
        const float4* p0 = reinterpret_cast<const float4*>(sIn[r]);
        const float4* p1 = reinterpret_cast<const float4*>(sIn[r + 1]);
        float a0 = bias, c0 = 0.f, a1 = bias, c1 = 0.f;   // 4 indep FMA chains
#pragma unroll
        for (int q = 0; q < 14; q++) {
            float4 v0 = p0[q], v1 = p1[q];
            float w0 = wreg[4 * q], w1 = wreg[4 * q + 1];
            float w2 = wreg[4 * q + 2], w3 = wreg[4 * q + 3];
            a0 += v0.x * w0; c0 += v0.y * w1; a0 += v0.z * w2; c0 += v0.w * w3;
            a1 += v1.x * w0; c1 += v1.y * w1; a1 += v1.z * w2; c1 += v1.w * w3;
        }
        int n = n0 + r;
        if (n     < NN) g_h[n * 128 + j]       = fmaxf(a0 + c0, 0.f);
        if (n + 1 < NN) g_h[(n + 1) * 128 + j] = fmaxf(a1 + c1, 0.f);
    }
}

// --- GEMM2: out = g_h @ W  (K=128, NO=64); sel picks g_p / g_r --------------
__global__ void __launch_bounds__(64) k_gemm2(const float* __restrict__ W, int sel) {
    __shared__ float sH[32][128];                 // 16KB
    int j  = threadIdx.x;                         // output column 0..63
    int n0 = blockIdx.x * 32;
    float* __restrict__ out = sel ? g_r : g_p;

    float w[128];
#pragma unroll
    for (int f = 0; f < 128; f++) w[f] = W[f * 64 + j];

    for (int idx = threadIdx.x; idx < 32 * 128; idx += 64) {
        int r = idx >> 7, f = idx & 127;
        int n = n0 + r;
        sH[r][f] = (n < NN) ? g_h[n * 128 + f] : 0.f;
    }
    __syncthreads();

    for (int r = 0; r < 32; r += 2) {
        const float4* p0 = reinterpret_cast<const float4*>(sH[r]);
        const float4* p1 = reinterpret_cast<const float4*>(sH[r + 1]);
        float a0 = 0.f, c0 = 0.f, a1 = 0.f, c1 = 0.f;
#pragma unroll
        for (int q = 0; q < 32; q++) {
            float4 v0 = p0[q], v1 = p1[q];
            float w0 = w[4 * q], w1 = w[4 * q + 1];
            float w2 = w[4 * q + 2], w3 = w[4 * q + 3];
            a0 += v0.x * w0; c0 += v0.y * w1; a0 += v0.z * w2; c0 += v0.w * w3;
            a1 += v1.x * w0; c1 += v1.y * w1; a1 += v1.z * w2; c1 += v1.w * w3;
        }
        int n = n0 + r;
        if (n     < NN) out[n * 64 + j]       = a0 + c0;
        if (n + 1 < NN) out[(n + 1) * 64 + j] = a1 + c1;
    }
}

// --- layer-2 aggregation + epilogue: out = mean(p) + b2 + r -----------------
__global__ void k_agg2(const float* __restrict__ b2, float* __restrict__ out) {
    int w    = (blockIdx.x * blockDim.x + threadIdx.x) >> 5;
    int lane = threadIdx.x & 31;
    if (w >= NN) return;
    int start = g_off[w], cnt = g_cnt[w];
    float a0 = 0.f, a1 = 0.f;
    int k = 0;
    for (; k + 2 <= cnt; k += 2) {
        int s0 = g_csr[start + k], s1 = g_csr[start + k + 1];
        a0 += g_p[s0 * 64 + lane]      + g_p[s1 * 64 + lane];
        a1 += g_p[s0 * 64 + 32 + lane] + g_p[s1 * 64 + 32 + lane];
    }
    if (k < cnt) {
        int s0 = g_csr[start + k];
        a0 += g_p[s0 * 64 + lane];
        a1 += g_p[s0 * 64 + 32 + lane];
    }
    float inv = 1.f / (float)(cnt > 0 ? cnt : 1);
    int base = w * 64;
    out[base + lane]      = a0 * inv + b2[lane]      + g_r[base + lane];
    out[base + 32 + lane] = a1 * inv + b2[32 + lane] + g_r[base + 32 + lane];
}

extern "C" void kernel_launch(void* const* d_in, const int* in_sizes, int n_in,
                              void* d_out, int out_size) {
    const float* x   = (const float*)d_in[0];
    const int*   e   = (const int*)d_in[1];
    const float* W1l = (const float*)d_in[2];
    const float* b1  = (const float*)d_in[3];
    const float* W1r = (const float*)d_in[4];
    const float* W2l = (const float*)d_in[5];
    const float* b2  = (const float*)d_in[6];
    const float* W2r = (const float*)d_in[7];
    float* out = (float*)d_out;
    int E = in_sizes[1] / 2;

    int nb = (NN + 1023) / 1024;

    k_detect<<<1, 64>>>(e);
    k_zero  <<<(NN + 255) / 256, 256>>>();
    k_count <<<(E + 255) / 256, 256>>>(e, E);
    k_scan_a<<<nb, 1024>>>();
    k_scan_b<<<1, 32>>>(nb);
    k_scan_c<<<(NN + 255) / 256, 256>>>();
    k_bucket<<<(E + 255) / 256, 256>>>(e, E);
    k_agg1  <<<(NN + 7) / 8, 256>>>(x);                 // 8 warps/block
    k_gemm1 <<<(NN + 63) / 64, 128>>>(x, W1l, b1, W1r);
    k_gemm2 <<<(NN + 31) / 32, 64>>>(W2l, 0);           // g_p
    k_gemm2 <<<(NN + 31) / 32, 64>>>(W2r, 1);           // g_r
    k_agg2  <<<(NN + 7) / 8, 256>>>(b2, out);
}

// round 3
// speedup vs baseline: 1.0801x; 1.0801x over previous
#include <cuda_runtime.h>
#include <cuda_bf16.h>

// ---------------------------------------------------------------------------
// GraphSAGE 2-layer (mean aggregation), N=100000 nodes, F: 27 -> 128 -> 64.
//
//   1. detect edge_index dtype (int32 vs int64) on device
//   2. build CSR by dst: count -> 2-level exclusive scan -> bucket scatter
//   3. agg1[n,27]  = mean_{e: dst=n} x[src]               (gather, no fp atomics)
//   4. h[n,128]    = relu(agg1 @ W1_l + x @ W1_r + b1)    (FFMA2 reg-weight GEMM)
//   5. p[n,64] = h @ W2_l ; r[n,64] = h @ W2_r            (one merged FFMA2 GEMM)
//   6. out[n,64]   = mean_{e: dst=n} p[src] + b2 + r[n]   (gather + epilogue)
//
// GEMMs use packed fp32 FMA (PTX fma.rn.f32x2 -> SASS FFMA2): 2 fp32 FMA per
// lane-instruction vs 1 for scalar FFMA.
// ---------------------------------------------------------------------------

#define NN   100000
#define ECAP 1700000

static __device__ int   g_is64;
static __device__ int   g_cnt[NN];
static __device__ int   g_off[NN];
static __device__ int   g_cur[NN];
static __device__ int   g_part[128];
static __device__ int   g_csr[ECAP];
static __device__ float g_agg1[NN * 28];     // padded row: [27]=0
static __device__ float g_h[NN * 128];
static __device__ float g_p[NN * 64];
static __device__ float g_r[NN * 64];

typedef unsigned long long u64;

__device__ __forceinline__ u64 pack2(float lo, float hi) {
    u64 r;
    asm("mov.b64 %0, {%1, %2};" : "=l"(r) : "f"(lo), "f"(hi));
    return r;
}
__device__ __forceinline__ float2 unpack2(u64 v) {
    float2 r;
    asm("mov.b64 {%0, %1}, %2;" : "=f"(r.x), "=f"(r.y) : "l"(v));
    return r;
}
__device__ __forceinline__ void fma2(u64& acc, u64 a, u64 b) {
    asm("fma.rn.f32x2 %0, %1, %2, %0;" : "+l"(acc) : "l"(a), "l"(b));
}

__device__ __forceinline__ int eidx(const int* __restrict__ e, int elem, int is64) {
    return is64 ? e[2 * elem] : e[elem];       // LE: low word of int64
}

// --- dtype detection: int64 values < 2^31 have zero high words --------------
__global__ void k_detect(const int* __restrict__ e) {
    __shared__ int s;
    if (threadIdx.x == 0) s = 0;
    __syncthreads();
    if (e[2 * threadIdx.x + 1] != 0) atomicOr(&s, 1);
    __syncthreads();
    if (threadIdx.x == 0) g_is64 = (s == 0);
}

__global__ void k_zero() {
    int i = blockIdx.x * blockDim.x + threadIdx.x;
    if (i < NN) g_cnt[i] = 0;
}

__global__ void k_count(const int* __restrict__ e, int E) {
    int i = blockIdx.x * blockDim.x + threadIdx.x;
    if (i >= E) return;
    atomicAdd(&g_cnt[eidx(e, E + i, g_is64)], 1);
}

// --- 2-level exclusive scan of g_cnt -> g_off -------------------------------
__global__ void k_scan_a() {
    __shared__ int s[1024];
    int tid = threadIdx.x;
    int i = blockIdx.x * 1024 + tid;
    int v = (i < NN) ? g_cnt[i] : 0;
    s[tid] = v;
    __syncthreads();
    for (int off = 1; off < 1024; off <<= 1) {
        int t = (tid >= off) ? s[tid - off] : 0;
        __syncthreads();
        s[tid] += t;
        __syncthreads();
    }
    if (i < NN) g_off[i] = s[tid] - v;
    if (tid == 1023) g_part[blockIdx.x] = s[1023];
}

__global__ void k_scan_b(int nb) {
    if (threadIdx.x == 0) {
        int run = 0;
        for (int b = 0; b < nb; b++) { int t = g_part[b]; g_part[b] = run; run += t; }
    }
}

__global__ void k_scan_c() {
    int i = blockIdx.x * blockDim.x + threadIdx.x;
    if (i >= NN) return;
    int o = g_off[i] + g_part[i >> 10];
    g_off[i] = o;
    g_cur[i] = o;
}

__global__ void k_bucket(const int* __restrict__ e, int E) {
    int i = blockIdx.x * blockDim.x + threadIdx.x;
    if (i >= E) return;
    int is64 = g_is64;
    int s = eidx(e, i, is64);
    int d = eidx(e, E + i, is64);
    int pos = atomicAdd(&g_cur[d], 1);
    g_csr[pos] = s;
}

// --- layer-1 aggregation: warp per node, lane = feature ---------------------
__global__ void k_agg1(const float* __restrict__ x) {
    int w    = (blockIdx.x * blockDim.x + threadIdx.x) >> 5;
    int lane = threadIdx.x & 31;
    if (w >= NN) return;
    int start = g_off[w], cnt = g_cnt[w];
    int lf = (lane < 27) ? lane : 0;
    float acc = 0.f;
    int k = 0;
    for (; k + 4 <= cnt; k += 4) {
        int s0 = g_csr[start + k],     s1 = g_csr[start + k + 1];
        int s2 = g_csr[start + k + 2], s3 = g_csr[start + k + 3];
        float v0 = x[s0 * 27 + lf], v1 = x[s1 * 27 + lf];
        float v2 = x[s2 * 27 + lf], v3 = x[s3 * 27 + lf];
        acc += (v0 + v1) + (v2 + v3);
    }
    for (; k < cnt; k++) acc += x[g_csr[start + k] * 27 + lf];
    float inv = 1.f / (float)(cnt > 0 ? cnt : 1);
    if (lane < 28) g_agg1[w * 28 + lane] = (lane < 27) ? acc * inv : 0.f;
}

// --- GEMM1: h = relu([agg1|x] @ [W1_l;W1_r] + b1), FFMA2 --------------------
__global__ void __launch_bounds__(128) k_gemm1(
    const float* __restrict__ x, const float* __restrict__ W1l,
    const float* __restrict__ b1, const float* __restrict__ W1r) {
    __shared__ __align__(16) float sIn[64][56];   // [node][agg(28)|x(28)] 14.3KB
    int j  = threadIdx.x;                         // output column 0..127
    int n0 = blockIdx.x * 64;

    // 56-row weight column packed into 28 f32x2 regs
    float wf[56];
#pragma unroll
    for (int f = 0; f < 27; f++) {
        wf[f]      = W1l[f * 128 + j];
        wf[28 + f] = W1r[f * 128 + j];
    }
    wf[27] = 0.f; wf[55] = 0.f;
    u64 w2[28];
#pragma unroll
    for (int q = 0; q < 28; q++) w2[q] = pack2(wf[2 * q], wf[2 * q + 1]);
    float bias = b1[j];

    // agg rows (28 floats, 16B-aligned) staged as float4
    {
        const float4* src = reinterpret_cast<const float4*>(g_agg1);
        for (int idx = threadIdx.x; idx < 64 * 7; idx += 128) {
            int r = idx / 7, q = idx % 7;
            int n = n0 + r;
            float4 v = (n < NN) ? src[n * 7 + q] : make_float4(0.f, 0.f, 0.f, 0.f);
            *reinterpret_cast<float4*>(&sIn[r][4 * q]) = v;
        }
    }
    // x rows (27 floats, unaligned stride) staged scalar
    for (int idx = threadIdx.x; idx < 64 * 28; idx += 128) {
        int r = idx / 28, f = idx % 28;
        int n = n0 + r;
        sIn[r][28 + f] = (n < NN && f < 27) ? x[n * 27 + f] : 0.f;
    }
    __syncthreads();

    for (int r = 0; r < 64; r += 2) {
        const ulonglong2* p0 = reinterpret_cast<const ulonglong2*>(sIn[r]);
        const ulonglong2* p1 = reinterpret_cast<const ulonglong2*>(sIn[r + 1]);
        u64 a0 = 0, c0 = 0, a1 = 0, c1 = 0;      // 4 indep FFMA2 chains
#pragma unroll
        for (int q = 0; q < 14; q++) {
            ulonglong2 v0 = p0[q], v1 = p1[q];
            u64 wA = w2[2 * q], wB = w2[2 * q + 1];
            fma2(a0, v0.x, wA); fma2(c0, v0.y, wB);
            fma2(a1, v1.x, wA); fma2(c1, v1.y, wB);
        }
        float2 fa0 = unpack2(a0), fc0 = unpack2(c0);
        float2 fa1 = unpack2(a1), fc1 = unpack2(c1);
        int n = n0 + r;
        if (n < NN)
            g_h[n * 128 + j] = fmaxf((fa0.x + fa0.y) + (fc0.x + fc0.y) + bias, 0.f);
        if (n + 1 < NN)
            g_h[(n + 1) * 128 + j] = fmaxf((fa1.x + fa1.y) + (fc1.x + fc1.y) + bias, 0.f);
    }
}

// --- GEMM2 merged: lanes 0-63 -> p = h@W2l, lanes 64-127 -> r = h@W2r -------
__global__ void __launch_bounds__(128) k_gemm2(
    const float* __restrict__ W2l, const float* __restrict__ W2r) {
    __shared__ __align__(16) float sH[64][128];   // 32KB
    int t  = threadIdx.x;
    int j  = t & 63;                              // output column 0..63
    int n0 = blockIdx.x * 64;
    const float* __restrict__ W   = (t < 64) ? W2l : W2r;
    float* __restrict__       out = (t < 64) ? g_p : g_r;

    u64 w2[64];                                   // 128-row weight column packed
#pragma unroll
    for (int q = 0; q < 64; q++)
        w2[q] = pack2(W[(2 * q) * 64 + j], W[(2 * q + 1) * 64 + j]);

    // float4-vectorized staging of 64 h-rows (LDG.128/STS.128)
    {
        const float4* src = reinterpret_cast<const float4*>(g_h);
        float4* dst = reinterpret_cast<float4*>(sH);
        for (int idx = threadIdx.x; idx < 64 * 32; idx += 128) {
            int n = n0 + (idx >> 5);
            dst[idx] = (n < NN) ? src[n * 32 + (idx & 31)]
                                : make_float4(0.f, 0.f, 0.f, 0.f);
        }
    }
    __syncthreads();

    for (int r = 0; r < 64; r++) {
        const ulonglong2* p = reinterpret_cast<const ulonglong2*>(sH[r]);
        u64 a0 = 0, a1 = 0;                       // 2 chains x 32 FFMA2
#pragma unroll
        for (int q = 0; q < 32; q++) {
            ulonglong2 v = p[q];
            fma2(a0, v.x, w2[2 * q]);
            fma2(a1, v.y, w2[2 * q + 1]);
        }
        int n = n0 + r;
        if (n < NN) {
            float2 f0 = unpack2(a0), f1 = unpack2(a1);
            out[n * 64 + j] = (f0.x + f0.y) + (f1.x + f1.y);
        }
    }
}

// --- layer-2 aggregation + epilogue: out = mean(p) + b2 + r -----------------
__global__ void k_agg2(const float* __restrict__ b2, float* __restrict__ out) {
    int w    = (blockIdx.x * blockDim.x + threadIdx.x) >> 5;
    int lane = threadIdx.x & 31;
    if (w >= NN) return;
    int start = g_off[w], cnt = g_cnt[w];
    float a0 = 0.f, a1 = 0.f;
    int k = 0;
    for (; k + 2 <= cnt; k += 2) {
        int s0 = g_csr[start + k], s1 = g_csr[start + k + 1];
        a0 += g_p[s0 * 64 + lane]      + g_p[s1 * 64 + lane];
        a1 += g_p[s0 * 64 + 32 + lane] + g_p[s1 * 64 + 32 + lane];
    }
    if (k < cnt) {
        int s0 = g_csr[start + k];
        a0 += g_p[s0 * 64 + lane];
        a1 += g_p[s0 * 64 + 32 + lane];
    }
    float inv = 1.f / (float)(cnt > 0 ? cnt : 1);
    int base = w * 64;
    out[base + lane]      = a0 * inv + b2[lane]      + g_r[base + lane];
    out[base + 32 + lane] = a1 * inv + b2[32 + lane] + g_r[base + 32 + lane];
}

extern "C" void kernel_launch(void* const* d_in, const int* in_sizes, int n_in,
                              void* d_out, int out_size) {
    const float* x   = (const float*)d_in[0];
    const int*   e   = (const int*)d_in[1];
    const float* W1l = (const float*)d_in[2];
    const float* b1  = (const float*)d_in[3];
    const float* W1r = (const float*)d_in[4];
    const float* W2l = (const float*)d_in[5];
    const float* b2  = (const float*)d_in[6];
    const float* W2r = (const float*)d_in[7];
    float* out = (float*)d_out;
    int E = in_sizes[1] / 2;

    int nb = (NN + 1023) / 1024;

    k_detect<<<1, 64>>>(e);
    k_zero  <<<(NN + 255) / 256, 256>>>();
    k_count <<<(E + 255) / 256, 256>>>(e, E);
    k_scan_a<<<nb, 1024>>>();
    k_scan_b<<<1, 32>>>(nb);
    k_scan_c<<<(NN + 255) / 256, 256>>>();
    k_bucket<<<(E + 255) / 256, 256>>>(e, E);
    k_agg1  <<<(NN + 7) / 8, 256>>>(x);
    k_gemm1 <<<(NN + 63) / 64, 128>>>(x, W1l, b1, W1r);
    k_gemm2 <<<(NN + 63) / 64, 128>>>(W2l, W2r);
    k_agg2  <<<(NN + 7) / 8, 256>>>(b2, out);
}

// round 4
// speedup vs baseline: 1.1739x; 1.0868x over previous
#include <cuda_runtime.h>
#include <cuda_bf16.h>

// ---------------------------------------------------------------------------
// GraphSAGE 2-layer (mean aggregation), N=100000 nodes, F: 27 -> 128 -> 64.
//
//   1. detect edge_index dtype (int32 vs int64) on device
//   2. build CSR by dst: count -> 2-level exclusive scan -> bucket scatter
//   3. agg1[n,27]  = mean_{e: dst=n} x[src]               (gather, no fp atomics)
//   4. FUSED persistent GEMM (weights in regs, loaded once per block):
//        h[64,128] tile = relu([agg1|x] @ [W1_l;W1_r] + b1)   -> smem
//        p = h @ W2_l ; r = h @ W2_r                          -> gmem
//   5. out[n,64]   = mean_{e: dst=n} p[src] + b2 + r[n]   (float2 gather)
//
// GEMMs use packed fp32 FMA (PTX fma.rn.f32x2 -> SASS FFMA2).
// ---------------------------------------------------------------------------

#define NN   100000
#define ECAP 1700000
#define NT   ((NN + 63) / 64)          // 1563 tiles of 64 nodes
#define GGRID 296                      // persistent gemm grid (2 blocks/SM)

static __device__ int   g_is64;
static __device__ int   g_cnt[NN];
static __device__ int   g_off[NN];
static __device__ int   g_cur[NN];
static __device__ int   g_part[128];
static __device__ int   g_csr[ECAP];
static __device__ float g_agg1[NN * 28];     // padded row: [27]=0
static __device__ float g_p[NN * 64];
static __device__ float g_r[NN * 64];

typedef unsigned long long u64;

__device__ __forceinline__ u64 pack2(float lo, float hi) {
    u64 r;
    asm("mov.b64 %0, {%1, %2};" : "=l"(r) : "f"(lo), "f"(hi));
    return r;
}
__device__ __forceinline__ float2 unpack2(u64 v) {
    float2 r;
    asm("mov.b64 {%0, %1}, %2;" : "=f"(r.x), "=f"(r.y) : "l"(v));
    return r;
}
__device__ __forceinline__ void fma2(u64& acc, u64 a, u64 b) {
    asm("fma.rn.f32x2 %0, %1, %2, %0;" : "+l"(acc) : "l"(a), "l"(b));
}

__device__ __forceinline__ int eidx(const int* __restrict__ e, int elem, int is64) {
    return is64 ? e[2 * elem] : e[elem];       // LE: low word of int64
}

// --- dtype detection: int64 values < 2^31 have zero high words --------------
__global__ void k_detect(const int* __restrict__ e) {
    __shared__ int s;
    if (threadIdx.x == 0) s = 0;
    __syncthreads();
    if (e[2 * threadIdx.x + 1] != 0) atomicOr(&s, 1);
    __syncthreads();
    if (threadIdx.x == 0) g_is64 = (s == 0);
}

__global__ void k_zero() {
    int i = blockIdx.x * blockDim.x + threadIdx.x;
    if (i < NN) g_cnt[i] = 0;
}

__global__ void k_count(const int* __restrict__ e, int E) {
    int i = blockIdx.x * blockDim.x + threadIdx.x;
    if (i >= E) return;
    atomicAdd(&g_cnt[eidx(e, E + i, g_is64)], 1);
}

// --- 2-level exclusive scan of g_cnt -> g_off -------------------------------
__global__ void k_scan_a() {
    __shared__ int s[1024];
    int tid = threadIdx.x;
    int i = blockIdx.x * 1024 + tid;
    int v = (i < NN) ? g_cnt[i] : 0;
    s[tid] = v;
    __syncthreads();
    for (int off = 1; off < 1024; off <<= 1) {
        int t = (tid >= off) ? s[tid - off] : 0;
        __syncthreads();
        s[tid] += t;
        __syncthreads();
    }
    if (i < NN) g_off[i] = s[tid] - v;
    if (tid == 1023) g_part[blockIdx.x] = s[1023];
}

__global__ void k_scan_b(int nb) {
    if (threadIdx.x == 0) {
        int run = 0;
        for (int b = 0; b < nb; b++) { int t = g_part[b]; g_part[b] = run; run += t; }
    }
}

__global__ void k_scan_c() {
    int i = blockIdx.x * blockDim.x + threadIdx.x;
    if (i >= NN) return;
    int o = g_off[i] + g_part[i >> 10];
    g_off[i] = o;
    g_cur[i] = o;
}

__global__ void k_bucket(const int* __restrict__ e, int E) {
    int i = blockIdx.x * blockDim.x + threadIdx.x;
    if (i >= E) return;
    int is64 = g_is64;
    int s = eidx(e, i, is64);
    int d = eidx(e, E + i, is64);
    int pos = atomicAdd(&g_cur[d], 1);
    g_csr[pos] = s;
}

// --- layer-1 aggregation: warp per node, lane = feature ---------------------
__global__ void k_agg1(const float* __restrict__ x) {
    int w    = (blockIdx.x * blockDim.x + threadIdx.x) >> 5;
    int lane = threadIdx.x & 31;
    if (w >= NN) return;
    int start = g_off[w], cnt = g_cnt[w];
    int lf = (lane < 27) ? lane : 0;
    float acc = 0.f;
    int k = 0;
    for (; k + 4 <= cnt; k += 4) {
        int s0 = g_csr[start + k],     s1 = g_csr[start + k + 1];
        int s2 = g_csr[start + k + 2], s3 = g_csr[start + k + 3];
        float v0 = x[s0 * 27 + lf], v1 = x[s1 * 27 + lf];
        float v2 = x[s2 * 27 + lf], v3 = x[s3 * 27 + lf];
        acc += (v0 + v1) + (v2 + v3);
    }
    for (; k < cnt; k++) acc += x[g_csr[start + k] * 27 + lf];
    float inv = 1.f / (float)(cnt > 0 ? cnt : 1);
    if (lane < 28) g_agg1[w * 28 + lane] = (lane < 27) ? acc * inv : 0.f;
}

// --- FUSED persistent GEMM ---------------------------------------------------
// Block loads W1 column j (56 rows -> 28 u64) and W2 column (128 rows -> 64 u64)
// ONCE, then loops over 64-node tiles:
//   stage sIn=[agg1|x] -> h tile into sH (relu) -> p/r from sH -> gmem.
// Thread j: phase1 computes h col j; phase2: t<64 -> p col t, t>=64 -> r col t-64.
__global__ void __launch_bounds__(128) k_gemm_fused(
    const float* __restrict__ x, const float* __restrict__ W1l,
    const float* __restrict__ b1, const float* __restrict__ W1r,
    const float* __restrict__ W2l, const float* __restrict__ W2r) {
    __shared__ __align__(16) float sIn[64][56];   // 14.3KB
    __shared__ __align__(16) float sH[64][128];   // 32KB
    int j = threadIdx.x;

    // W1 column j (once per block)
    u64 w1[28];
    {
        float wf[56];
#pragma unroll
        for (int f = 0; f < 27; f++) {
            wf[f]      = W1l[f * 128 + j];
            wf[28 + f] = W1r[f * 128 + j];
        }
        wf[27] = 0.f; wf[55] = 0.f;
#pragma unroll
        for (int q = 0; q < 28; q++) w1[q] = pack2(wf[2 * q], wf[2 * q + 1]);
    }
    float bias = b1[j];

    // W2 column (once per block): t<64 -> W2l col t, else W2r col t-64
    int j2 = j & 63;
    const float* __restrict__ W2  = (j < 64) ? W2l : W2r;
    float* __restrict__       out = (j < 64) ? g_p : g_r;
    u64 w2[64];
#pragma unroll
    for (int q = 0; q < 64; q++)
        w2[q] = pack2(W2[(2 * q) * 64 + j2], W2[(2 * q + 1) * 64 + j2]);

    for (int tile = blockIdx.x; tile < NT; tile += GGRID) {
        int n0 = tile * 64;

        // ---- stage inputs --------------------------------------------------
        {
            const float4* src = reinterpret_cast<const float4*>(g_agg1);
            for (int idx = threadIdx.x; idx < 64 * 7; idx += 128) {
                int r = idx / 7, q = idx % 7;
                int n = n0 + r;
                float4 v = (n < NN) ? src[n * 7 + q] : make_float4(0.f, 0.f, 0.f, 0.f);
                *reinterpret_cast<float4*>(&sIn[r][4 * q]) = v;
            }
            for (int idx = threadIdx.x; idx < 64 * 28; idx += 128) {
                int r = idx / 28, f = idx % 28;
                int n = n0 + r;
                sIn[r][28 + f] = (n < NN && f < 27) ? x[n * 27 + f] : 0.f;
            }
        }
        __syncthreads();

        // ---- phase 1: h = relu([agg|x] @ W1 + b1) -> sH --------------------
        for (int r = 0; r < 64; r += 2) {
            const ulonglong2* p0 = reinterpret_cast<const ulonglong2*>(sIn[r]);
            const ulonglong2* p1 = reinterpret_cast<const ulonglong2*>(sIn[r + 1]);
            u64 a0 = 0, c0 = 0, a1 = 0, c1 = 0;
#pragma unroll
            for (int q = 0; q < 14; q++) {
                ulonglong2 v0 = p0[q], v1 = p1[q];
                u64 wA = w1[2 * q], wB = w1[2 * q + 1];
                fma2(a0, v0.x, wA); fma2(c0, v0.y, wB);
                fma2(a1, v1.x, wA); fma2(c1, v1.y, wB);
            }
            float2 fa0 = unpack2(a0), fc0 = unpack2(c0);
            float2 fa1 = unpack2(a1), fc1 = unpack2(c1);
            sH[r][j]     = fmaxf((fa0.x + fa0.y) + (fc0.x + fc0.y) + bias, 0.f);
            sH[r + 1][j] = fmaxf((fa1.x + fa1.y) + (fc1.x + fc1.y) + bias, 0.f);
        }
        __syncthreads();

        // ---- phase 2: p/r = h @ W2 -> gmem ---------------------------------
        for (int r = 0; r < 64; r++) {
            const ulonglong2* p = reinterpret_cast<const ulonglong2*>(sH[r]);
            u64 a0 = 0, a1 = 0;
#pragma unroll
            for (int q = 0; q < 32; q++) {
                ulonglong2 v = p[q];
                fma2(a0, v.x, w2[2 * q]);
                fma2(a1, v.y, w2[2 * q + 1]);
            }
            int n = n0 + r;
            if (n < NN) {
                float2 f0 = unpack2(a0), f1 = unpack2(a1);
                out[n * 64 + j2] = (f0.x + f0.y) + (f1.x + f1.y);
            }
        }
        __syncthreads();   // protect sH/sIn before next tile
    }
}

// --- layer-2 aggregation + epilogue: out = mean(p) + b2 + r, float2 lanes ---
__global__ void k_agg2(const float* __restrict__ b2, float* __restrict__ out) {
    int w    = (blockIdx.x * blockDim.x + threadIdx.x) >> 5;
    int lane = threadIdx.x & 31;
    if (w >= NN) return;
    int start = g_off[w], cnt = g_cnt[w];
    const float2* __restrict__ p2 = reinterpret_cast<const float2*>(g_p);
    float ax = 0.f, ay = 0.f;
    int k = 0;
    for (; k + 2 <= cnt; k += 2) {
        int s0 = g_csr[start + k], s1 = g_csr[start + k + 1];
        float2 v0 = p2[s0 * 32 + lane];
        float2 v1 = p2[s1 * 32 + lane];
        ax += v0.x + v1.x;
        ay += v0.y + v1.y;
    }
    if (k < cnt) {
        float2 v0 = p2[g_csr[start + k] * 32 + lane];
        ax += v0.x; ay += v0.y;
    }
    float inv = 1.f / (float)(cnt > 0 ? cnt : 1);
    const float2* __restrict__ b22 = reinterpret_cast<const float2*>(b2);
    const float2* __restrict__ r2  = reinterpret_cast<const float2*>(g_r);
    float2 bv = b22[lane];
    float2 rv = r2[w * 32 + lane];
    float2 o;
    o.x = ax * inv + bv.x + rv.x;
    o.y = ay * inv + bv.y + rv.y;
    reinterpret_cast<float2*>(out)[w * 32 + lane] = o;
}

extern "C" void kernel_launch(void* const* d_in, const int* in_sizes, int n_in,
                              void* d_out, int out_size) {
    const float* x   = (const float*)d_in[0];
    const int*   e   = (const int*)d_in[1];
    const float* W1l = (const float*)d_in[2];
    const float* b1  = (const float*)d_in[3];
    const float* W1r = (const float*)d_in[4];
    const float* W2l = (const float*)d_in[5];
    const float* b2  = (const float*)d_in[6];
    const float* W2r = (const float*)d_in[7];
    float* out = (float*)d_out;
    int E = in_sizes[1] / 2;

    int nb = (NN + 1023) / 1024;

    k_detect<<<1, 64>>>(e);
    k_zero  <<<(NN + 255) / 256, 256>>>();
    k_count <<<(E + 255) / 256, 256>>>(e, E);
    k_scan_a<<<nb, 1024>>>();
    k_scan_b<<<1, 32>>>(nb);
    k_scan_c<<<(NN + 255) / 256, 256>>>();
    k_bucket<<<(E + 255) / 256, 256>>>(e, E);
    k_agg1  <<<(NN + 7) / 8, 256>>>(x);
    k_gemm_fused<<<GGRID, 128>>>(x, W1l, b1, W1r, W2l, W2r);
    k_agg2  <<<(NN + 7) / 8, 256>>>(b2, out);
}